// round 1
// baseline (speedup 1.0000x reference)
#include <cuda_runtime.h>

typedef unsigned long long ull;

// Problem shapes (fixed by setup_inputs)
#define Hh   256
#define Kk   4096
#define Bb   2
#define Nn   256    // S*S
#define DD   2048   // D = H*d
#define QB   128    // queries per block
#define NPAIR 2048  // K/2 codeword pairs
#define ROWB 80     // bytes per ct row: 64B interleaved pair data + 8B half-norms + 8B pad

#define CT_BYTES   (NPAIR * ROWB)          // 163840
#define XS_OFF     CT_BYTES
#define XS_BYTES   (QB * 64)               // 8192: per query 8 dup-f32x2
#define PART_OFF   (XS_OFF + XS_BYTES)
#define PART_BYTES (16 * QB * 8)           // 16384
#define SMEM_TOTAL (PART_OFF + PART_BYTES) // 188416

__device__ __forceinline__ ull ffma2(ull a, ull b, ull c) {
    ull d;
    asm("fma.rn.f32x2 %0, %1, %2, %3;" : "=l"(d) : "l"(a), "l"(b), "l"(c));
    return d;
}

__global__ __launch_bounds__(512, 1)
void vq_kernel(const float* __restrict__ emb,
               const float* __restrict__ cb,
               float* __restrict__ out) {
    extern __shared__ char smem[];
    const int h  = blockIdx.x >> 2;
    const int qc = blockIdx.x & 3;
    const int tid = threadIdx.x;

    // ---- stage queries: xs[j][dd] = {-x, -x} (duplicated for packed FMA) ----
    float* xs = (float*)(smem + XS_OFF);
    for (int i = tid; i < QB * 8; i += 512) {
        int j = i >> 3, dd = i & 7;
        int g = qc * QB + j;
        int b = g >> 8, n = g & 255;
        float v = emb[((size_t)(b * DD + h * 8 + dd)) * Nn + n];
        ((float2*)xs)[j * 8 + dd] = make_float2(-v, -v);
    }

    // ---- stage codebook: ct[kp] row = 8 x {c[2kp][dd], c[2kp+1][dd]} + {hc0, hc1} ----
    char* ct = smem;
    const float4* csrc = (const float4*)(cb + (size_t)h * Kk * 8);
    for (int kp = tid; kp < NPAIR; kp += 512) {
        float4 a0 = csrc[kp * 4 + 0];
        float4 a1 = csrc[kp * 4 + 1];
        float4 a2 = csrc[kp * 4 + 2];
        float4 a3 = csrc[kp * 4 + 3];
        float s0 = a0.x * a0.x;
        s0 = fmaf(a0.y, a0.y, s0); s0 = fmaf(a0.z, a0.z, s0); s0 = fmaf(a0.w, a0.w, s0);
        s0 = fmaf(a1.x, a1.x, s0); s0 = fmaf(a1.y, a1.y, s0); s0 = fmaf(a1.z, a1.z, s0);
        s0 = fmaf(a1.w, a1.w, s0);
        float s1 = a2.x * a2.x;
        s1 = fmaf(a2.y, a2.y, s1); s1 = fmaf(a2.z, a2.z, s1); s1 = fmaf(a2.w, a2.w, s1);
        s1 = fmaf(a3.x, a3.x, s1); s1 = fmaf(a3.y, a3.y, s1); s1 = fmaf(a3.z, a3.z, s1);
        s1 = fmaf(a3.w, a3.w, s1);
        char* row = ct + kp * ROWB;
        ((float4*)row)[0] = make_float4(a0.x, a2.x, a0.y, a2.y);
        ((float4*)row)[1] = make_float4(a0.z, a2.z, a0.w, a2.w);
        ((float4*)row)[2] = make_float4(a1.x, a3.x, a1.y, a3.y);
        ((float4*)row)[3] = make_float4(a1.z, a3.z, a1.w, a3.w);
        *((float2*)(row + 64)) = make_float2(s0 * 0.5f, s1 * 0.5f);
    }
    __syncthreads();

    // ---- main scan: warp w covers ks [w*256, w*256+256), lanes carry QR=4 queries ----
    const int w = tid >> 5, lane = tid & 31;

    ull xr[4][8];
#pragma unroll
    for (int q = 0; q < 4; q++) {
        const ulonglong2* xrow = (const ulonglong2*)(xs + (lane + (q << 5)) * 16);
#pragma unroll
        for (int t = 0; t < 4; t++) {
            ulonglong2 v = xrow[t];
            xr[q][2 * t]     = v.x;
            xr[q][2 * t + 1] = v.y;
        }
    }

    float best[4];
    int   bidx[4];
#pragma unroll
    for (int q = 0; q < 4; q++) { best[q] = 3.4028234663852886e38f; bidx[q] = 0; }

    const char* row = ct + (size_t)(w * 128) * ROWB;
#pragma unroll 1
    for (int kp = 0; kp < 128; kp++, row += ROWB) {
        ulonglong2 cA = ((const ulonglong2*)row)[0];
        ulonglong2 cB = ((const ulonglong2*)row)[1];
        ulonglong2 cC = ((const ulonglong2*)row)[2];
        ulonglong2 cD = ((const ulonglong2*)row)[3];
        ull ch = *((const ull*)(row + 64));
        int k0 = ((w << 7) + kp) << 1;
#pragma unroll
        for (int q = 0; q < 4; q++) {
            ull acc = ffma2(xr[q][0], cA.x, ch);
            acc = ffma2(xr[q][1], cA.y, acc);
            acc = ffma2(xr[q][2], cB.x, acc);
            acc = ffma2(xr[q][3], cB.y, acc);
            acc = ffma2(xr[q][4], cC.x, acc);
            acc = ffma2(xr[q][5], cC.y, acc);
            acc = ffma2(xr[q][6], cD.x, acc);
            acc = ffma2(xr[q][7], cD.y, acc);
            float lo = __uint_as_float((unsigned)acc);
            float hi = __uint_as_float((unsigned)(acc >> 32));
            if (lo < best[q]) { best[q] = lo; bidx[q] = k0; }
            if (hi < best[q]) { best[q] = hi; bidx[q] = k0 + 1; }
        }
    }

    // ---- merge across warps (ascending w => first-index tie-break preserved) ----
    __syncthreads();
    float2* part = (float2*)(smem + PART_OFF);
#pragma unroll
    for (int q = 0; q < 4; q++)
        part[(w << 7) + lane + (q << 5)] = make_float2(best[q], __int_as_float(bidx[q]));
    __syncthreads();

    if (tid < QB) {
        float2 p = part[tid];
        float bb = p.x;
        int   bi = __float_as_int(p.y);
#pragma unroll
        for (int ww = 1; ww < 16; ww++) {
            float2 c2 = part[(ww << 7) + tid];
            if (c2.x < bb) { bb = c2.x; bi = __float_as_int(c2.y); }
        }
        int g = qc * QB + tid;
        int b = g >> 8, n = g & 255;
        const char* crow = ct + (size_t)(bi >> 1) * ROWB;
        int hs = bi & 1;
#pragma unroll
        for (int dd = 0; dd < 8; dd++) {
            float qv = ((const float*)crow)[dd * 2 + hs];
            float xv = -xs[tid * 16 + dd * 2];              // stored as -x
            out[((size_t)(b * DD + h * 8 + dd)) * Nn + n] = xv + (qv - xv); // mimic ref rounding
        }
    }
}

extern "C" void kernel_launch(void* const* d_in, const int* in_sizes, int n_in,
                              void* d_out, int out_size) {
    const float* emb = (const float*)d_in[0];
    const float* cb  = (const float*)d_in[1];
    float* out = (float*)d_out;
    cudaFuncSetAttribute(vq_kernel, cudaFuncAttributeMaxDynamicSharedMemorySize, SMEM_TOTAL);
    vq_kernel<<<Hh * 4, 512, SMEM_TOTAL>>>(emb, cb, out);
}

// round 2
// speedup vs baseline: 1.0363x; 1.0363x over previous
#include <cuda_runtime.h>

typedef unsigned long long ull;

// Problem shapes (fixed by setup_inputs)
#define Hh   256
#define Kk   4096
#define Nn   256    // S*S
#define DD   2048   // D = H*d
#define QB   128    // queries per block
#define NPAIR 2048  // K/2 codeword pairs
#define ROWB 80     // bytes per ct row: 64B interleaved pair data + 8B half-norms + 8B pad

#define CT_BYTES   (NPAIR * ROWB)          // 163840
#define XS_OFF     CT_BYTES
#define XS_BYTES   (QB * 64)               // 8192: per query 8 dup-f32x2 (negated)
#define PART_OFF   (XS_OFF + XS_BYTES)
#define PART_BYTES (16 * QB * 8)           // 16384: [krange][qid] = {best, k}
#define SMEM_TOTAL (PART_OFF + PART_BYTES) // 188416

__device__ __forceinline__ ull ffma2(ull a, ull b, ull c) {
    ull d;
    asm("fma.rn.f32x2 %0, %1, %2, %3;" : "=l"(d) : "l"(a), "l"(b), "l"(c));
    return d;
}

__device__ __forceinline__ void score_pair(const ull* xr, const char* row,
                                           float& lo, float& hi) {
    ulonglong2 cA = ((const ulonglong2*)row)[0];
    ulonglong2 cB = ((const ulonglong2*)row)[1];
    ulonglong2 cC = ((const ulonglong2*)row)[2];
    ulonglong2 cD = ((const ulonglong2*)row)[3];
    ull ch = *((const ull*)(row + 64));
    ull acc = ffma2(xr[0], cA.x, ch);
    acc = ffma2(xr[1], cA.y, acc);
    acc = ffma2(xr[2], cB.x, acc);
    acc = ffma2(xr[3], cB.y, acc);
    acc = ffma2(xr[4], cC.x, acc);
    acc = ffma2(xr[5], cC.y, acc);
    acc = ffma2(xr[6], cD.x, acc);
    acc = ffma2(xr[7], cD.y, acc);
    lo = __uint_as_float((unsigned)acc);
    hi = __uint_as_float((unsigned)(acc >> 32));
}

__global__ __launch_bounds__(1024, 1)
void vq_kernel(const float* __restrict__ emb,
               const float* __restrict__ cb,
               float* __restrict__ out) {
    extern __shared__ char smem[];
    const int h  = blockIdx.x >> 2;
    const int qc = blockIdx.x & 3;
    const int tid = threadIdx.x;

    // ---- stage queries: xs[j][dd] = {-x, -x} (duplicated for packed FMA) ----
    float* xs = (float*)(smem + XS_OFF);
    for (int i = tid; i < QB * 8; i += 1024) {
        int j = i >> 3, dd = i & 7;
        int g = qc * QB + j;
        int b = g >> 8, n = g & 255;
        float v = emb[((size_t)(b * DD + h * 8 + dd)) * Nn + n];
        ((float2*)xs)[j * 8 + dd] = make_float2(-v, -v);
    }

    // ---- stage codebook: ct[kp] row = 8 x {c[2kp][dd], c[2kp+1][dd]} + {hc0, hc1} ----
    char* ct = smem;
    const float4* csrc = (const float4*)(cb + (size_t)h * Kk * 8);
    for (int kp = tid; kp < NPAIR; kp += 1024) {
        float4 a0 = csrc[kp * 4 + 0];
        float4 a1 = csrc[kp * 4 + 1];
        float4 a2 = csrc[kp * 4 + 2];
        float4 a3 = csrc[kp * 4 + 3];
        float s0 = a0.x * a0.x;
        s0 = fmaf(a0.y, a0.y, s0); s0 = fmaf(a0.z, a0.z, s0); s0 = fmaf(a0.w, a0.w, s0);
        s0 = fmaf(a1.x, a1.x, s0); s0 = fmaf(a1.y, a1.y, s0); s0 = fmaf(a1.z, a1.z, s0);
        s0 = fmaf(a1.w, a1.w, s0);
        float s1 = a2.x * a2.x;
        s1 = fmaf(a2.y, a2.y, s1); s1 = fmaf(a2.z, a2.z, s1); s1 = fmaf(a2.w, a2.w, s1);
        s1 = fmaf(a3.x, a3.x, s1); s1 = fmaf(a3.y, a3.y, s1); s1 = fmaf(a3.z, a3.z, s1);
        s1 = fmaf(a3.w, a3.w, s1);
        char* row = ct + kp * ROWB;
        ((float4*)row)[0] = make_float4(a0.x, a2.x, a0.y, a2.y);
        ((float4*)row)[1] = make_float4(a0.z, a2.z, a0.w, a2.w);
        ((float4*)row)[2] = make_float4(a1.x, a3.x, a1.y, a3.y);
        ((float4*)row)[3] = make_float4(a1.z, a3.z, a1.w, a3.w);
        *((float2*)(row + 64)) = make_float2(s0 * 0.5f, s1 * 0.5f);
    }
    __syncthreads();

    // ---- main scan ----
    // 32 warps: warp w -> query half (w & 1), k-range (w >> 1) of 256 ks (128 pairs).
    // Lane carries QR=2 queries: qid = whalf*64 + qr*32 + lane.
    const int w = tid >> 5, lane = tid & 31;
    const int whalf = w & 1, kr = w >> 1;

    ull xr0[8], xr1[8];
    {
        const int q0 = whalf * 64 + lane;
        const ulonglong2* xrow = (const ulonglong2*)(xs + q0 * 16);
#pragma unroll
        for (int t = 0; t < 4; t++) {
            ulonglong2 v = xrow[t];
            xr0[2 * t] = v.x; xr0[2 * t + 1] = v.y;
        }
        const ulonglong2* xrow1 = (const ulonglong2*)(xs + (q0 + 32) * 16);
#pragma unroll
        for (int t = 0; t < 4; t++) {
            ulonglong2 v = xrow1[t];
            xr1[2 * t] = v.x; xr1[2 * t + 1] = v.y;
        }
    }

    float best0 = 3.4028234663852886e38f, best1 = best0;
    int   bp0 = kr * 128, bp1 = bp0;

    const char* row = ct + (size_t)(kr * 128) * ROWB;
#pragma unroll 2
    for (int kp = kr * 128; kp < kr * 128 + 128; kp++, row += ROWB) {
        ulonglong2 cA = ((const ulonglong2*)row)[0];
        ulonglong2 cB = ((const ulonglong2*)row)[1];
        ulonglong2 cC = ((const ulonglong2*)row)[2];
        ulonglong2 cD = ((const ulonglong2*)row)[3];
        ull ch = *((const ull*)(row + 64));

        ull a0 = ffma2(xr0[0], cA.x, ch);
        ull a1 = ffma2(xr1[0], cA.x, ch);
        a0 = ffma2(xr0[1], cA.y, a0);
        a1 = ffma2(xr1[1], cA.y, a1);
        a0 = ffma2(xr0[2], cB.x, a0);
        a1 = ffma2(xr1[2], cB.x, a1);
        a0 = ffma2(xr0[3], cB.y, a0);
        a1 = ffma2(xr1[3], cB.y, a1);
        a0 = ffma2(xr0[4], cC.x, a0);
        a1 = ffma2(xr1[4], cC.x, a1);
        a0 = ffma2(xr0[5], cC.y, a0);
        a1 = ffma2(xr1[5], cC.y, a1);
        a0 = ffma2(xr0[6], cD.x, a0);
        a1 = ffma2(xr1[6], cD.x, a1);
        a0 = ffma2(xr0[7], cD.y, a0);
        a1 = ffma2(xr1[7], cD.y, a1);

        float m0 = fminf(__uint_as_float((unsigned)a0),
                         __uint_as_float((unsigned)(a0 >> 32)));
        float m1 = fminf(__uint_as_float((unsigned)a1),
                         __uint_as_float((unsigned)(a1 >> 32)));
        if (m0 < best0) { best0 = m0; bp0 = kp; }
        if (m1 < best1) { best1 = m1; bp1 = kp; }
    }

    // ---- resolve lo/hi half of winning pair (once per lane per q) ----
    float2* part = (float2*)(smem + PART_OFF);
    {
        float lo, hi;
        score_pair(xr0, ct + (size_t)bp0 * ROWB, lo, hi);
        int k0 = bp0 * 2 + ((hi < lo) ? 1 : 0);
        score_pair(xr1, ct + (size_t)bp1 * ROWB, lo, hi);
        int k1 = bp1 * 2 + ((hi < lo) ? 1 : 0);
        int q0 = whalf * 64 + lane;
        part[kr * QB + q0]      = make_float2(best0, __int_as_float(k0));
        part[kr * QB + q0 + 32] = make_float2(best1, __int_as_float(k1));
    }
    __syncthreads();

    // ---- merge across k-ranges (ascending => first-index tie-break preserved) ----
    if (tid < QB) {
        float2 p = part[tid];
        float bb = p.x;
        int   bi = __float_as_int(p.y);
#pragma unroll
        for (int rr = 1; rr < 16; rr++) {
            float2 c2 = part[rr * QB + tid];
            if (c2.x < bb) { bb = c2.x; bi = __float_as_int(c2.y); }
        }
        int g = qc * QB + tid;
        int b = g >> 8, n = g & 255;
        const char* crow = ct + (size_t)(bi >> 1) * ROWB;
        int hs = bi & 1;
#pragma unroll
        for (int dd = 0; dd < 8; dd++) {
            float qv = ((const float*)crow)[dd * 2 + hs];
            float xv = -xs[tid * 16 + dd * 2];              // stored as -x
            out[((size_t)(b * DD + h * 8 + dd)) * Nn + n] = xv + (qv - xv); // mimic ref rounding
        }
    }
}

extern "C" void kernel_launch(void* const* d_in, const int* in_sizes, int n_in,
                              void* d_out, int out_size) {
    const float* emb = (const float*)d_in[0];
    const float* cb  = (const float*)d_in[1];
    float* out = (float*)d_out;
    cudaFuncSetAttribute(vq_kernel, cudaFuncAttributeMaxDynamicSharedMemorySize, SMEM_TOTAL);
    vq_kernel<<<Hh * 4, 1024, SMEM_TOTAL>>>(emb, cb, out);
}